// round 7
// baseline (speedup 1.0000x reference)
#include <cuda_runtime.h>
#include <math.h>

typedef unsigned long long u64;

#define BB   32
#define CC   128
#define ICC  256
#define HWD  4096
#define HIDD 512

// ---------------- scratch (static __device__, no allocation) ----------------
__device__ float g_kpT[CC * ICC];              // k' transposed: [c][o]
__device__ float g_kb[ICC];                    // BN1 bias folded through k
__device__ float g_inv2[CC], g_beta2[CC];      // BN2 folded params
__device__ float g_rowmax[BB * ICC], g_rowsum[BB * ICC];
__device__ float g_h[(size_t)BB * ICC * HWD];  // 128 MiB attention map
__device__ float g_xr[(size_t)BB * CC * HWD];  // 64 MiB residual x + attn
__device__ float g_n[(size_t)BB * CC * HWD];   // 64 MiB BN2(xr) = conv1 input
__device__ float g_t[(size_t)BB * HIDD * HWD]; // 256 MiB hidden activations

// ---------------- f32x2 helpers (FFMA2: 2x FP32 rate on sm_103a) ------------
__device__ __forceinline__ u64 splat2(float v) {
    u64 r; unsigned int u = __float_as_uint(v);
    asm("mov.b64 %0, {%1, %1};" : "=l"(r) : "r"(u));
    return r;
}
__device__ __forceinline__ void fma2(u64& d, u64 a, u64 b) {
    asm("fma.rn.f32x2 %0, %1, %2, %0;" : "+l"(d) : "l"(a), "l"(b));
}
__device__ __forceinline__ void unpack2(u64 p, float& lo, float& hi) {
    unsigned int l, h;
    asm("mov.b64 {%0, %1}, %2;" : "=r"(l), "=r"(h) : "l"(p));
    lo = __uint_as_float(l); hi = __uint_as_float(h);
}

// ---------------- K0: fold BN1 into k, precompute BN2 params ----------------
__global__ void k_fold(const float* __restrict__ bn1_g, const float* __restrict__ bn1_b,
                       const float* __restrict__ bn1_m, const float* __restrict__ bn1_v,
                       const float* __restrict__ kmat,
                       const float* __restrict__ bn2_g, const float* __restrict__ bn2_b,
                       const float* __restrict__ bn2_m, const float* __restrict__ bn2_v) {
    __shared__ float inv1[CC], beta1[CC];
    int t = threadIdx.x;
    if (t < CC) {
        float iv = bn1_g[t] * rsqrtf(bn1_v[t] + 1e-5f);
        inv1[t] = iv;
        beta1[t] = bn1_b[t] - bn1_m[t] * iv;
        float iv2 = bn2_g[t] * rsqrtf(bn2_v[t] + 1e-6f);
        g_inv2[t] = iv2;
        g_beta2[t] = bn2_b[t] - bn2_m[t] * iv2;
    }
    __syncthreads();
    int o = t;  // 0..255
    float s = 0.f;
    for (int c = 0; c < CC; ++c) {
        float kv = kmat[o * CC + c];
        g_kpT[c * ICC + o] = kv * inv1[c];
        s += kv * beta1[c];
    }
    g_kb[o] = s;
}

// ---------------- K1: h[b,o,s] = kb[o] + sum_c k'[o,c] x[b,c,s] -------------
__global__ void k_gemm1(const float* __restrict__ x) {
    int b = blockIdx.z, o0 = blockIdx.y * 64, s0 = blockIdx.x * 128;
    int tid = threadIdx.x, ty = tid >> 4, tx = tid & 15;
    __shared__ float As[32][64];    // [kk][o_local]
    __shared__ float Bs[32][128];   // [kk][s_local]
    float acc[4][8];
#pragma unroll
    for (int i = 0; i < 4; ++i)
#pragma unroll
        for (int j = 0; j < 8; ++j) acc[i][j] = 0.f;
    const float* xb = x + (size_t)b * CC * HWD + s0;
    for (int kc = 0; kc < 4; ++kc) {
        for (int g = tid; g < 2048; g += 256) {
            int kk = g >> 6, ol = g & 63;
            As[kk][ol] = g_kpT[(kc * 32 + kk) * ICC + o0 + ol];
        }
        for (int g = tid; g < 4096; g += 256) {
            int kk = g >> 7, ss = g & 127;
            Bs[kk][ss] = xb[(size_t)(kc * 32 + kk) * HWD + ss];
        }
        __syncthreads();
#pragma unroll 8
        for (int kk = 0; kk < 32; ++kk) {
            float4 av = *(const float4*)&As[kk][ty * 4];
            float4 b0 = *(const float4*)&Bs[kk][tx * 8];
            float4 b1 = *(const float4*)&Bs[kk][tx * 8 + 4];
            float bj[8] = {b0.x, b0.y, b0.z, b0.w, b1.x, b1.y, b1.z, b1.w};
#pragma unroll
            for (int j = 0; j < 8; ++j) {
                acc[0][j] += av.x * bj[j]; acc[1][j] += av.y * bj[j];
                acc[2][j] += av.z * bj[j]; acc[3][j] += av.w * bj[j];
            }
        }
        __syncthreads();
    }
#pragma unroll
    for (int i = 0; i < 4; ++i) {
        int o = o0 + ty * 4 + i;
        float kb = g_kb[o];
        float* hp = &g_h[((size_t)b * ICC + o) * HWD + s0 + tx * 8];
        float4 r0 = make_float4(acc[i][0] + kb, acc[i][1] + kb, acc[i][2] + kb, acc[i][3] + kb);
        float4 r1 = make_float4(acc[i][4] + kb, acc[i][5] + kb, acc[i][6] + kb, acc[i][7] + kb);
        *(float4*)hp = r0;
        *(float4*)(hp + 4) = r1;
    }
}

// ---------------- K2: per-row (b,o) max & sum of exp over 4096 spatial ------
__global__ void k_rowstats() {
    int r = blockIdx.x;
    const float4* p = (const float4*)(g_h + (size_t)r * HWD);
    int t = threadIdx.x;
    float v[16];
#pragma unroll
    for (int k = 0; k < 4; ++k) {
        float4 f = p[t + k * 256];
        v[k * 4 + 0] = f.x; v[k * 4 + 1] = f.y; v[k * 4 + 2] = f.z; v[k * 4 + 3] = f.w;
    }
    float m = v[0];
#pragma unroll
    for (int i = 1; i < 16; ++i) m = fmaxf(m, v[i]);
    __shared__ float red[256];
    red[t] = m; __syncthreads();
    for (int off = 128; off > 0; off >>= 1) {
        if (t < off) red[t] = fmaxf(red[t], red[t + off]);
        __syncthreads();
    }
    float rmax = red[0];
    __syncthreads();
    float s = 0.f;
#pragma unroll
    for (int i = 0; i < 16; ++i) s += __expf(v[i] - rmax);
    red[t] = s; __syncthreads();
    for (int off = 128; off > 0; off >>= 1) {
        if (t < off) red[t] += red[t + off];
        __syncthreads();
    }
    if (t == 0) { g_rowmax[r] = rmax; g_rowsum[r] = red[0]; }
}

// -------- K3: softmax over spatial + per-head channel-sum normalization -----
__global__ void k_dnorm() {
    int s = blockIdx.x * 256 + threadIdx.x;
    int nh = blockIdx.y, b = blockIdx.z;
    __shared__ float smax[32], sinv[32];
    if (threadIdx.x < 32) {
        int rr = b * ICC + nh * 32 + threadIdx.x;
        smax[threadIdx.x] = g_rowmax[rr];
        sinv[threadIdx.x] = 1.0f / g_rowsum[rr];
    }
    __syncthreads();
    float e[32];
    float d = 0.f;
    float* base = g_h + ((size_t)b * ICC + nh * 32) * HWD + s;
#pragma unroll
    for (int c = 0; c < 32; ++c) {
        float val = __expf(base[(size_t)c * HWD] - smax[c]) * sinv[c];
        e[c] = val; d += val;
    }
    float w = 1.0f / (d + 1e-6f);
#pragma unroll
    for (int c = 0; c < 32; ++c) base[(size_t)c * HWD] = e[c] * w;
}

// ------ K4: xr = x + v@h2 ; n = BN2(xr) -- both written for conv stage ------
__global__ void k_gemm2(const float* __restrict__ x, const float* __restrict__ vmat) {
    int b = blockIdx.z, c0 = blockIdx.y * 64, s0 = blockIdx.x * 128;
    int tid = threadIdx.x, ty = tid >> 4, tx = tid & 15;
    __shared__ float As[32][65];   // [kk][c_local], padded
    __shared__ float Bs[32][128];
    float acc[4][8];
#pragma unroll
    for (int i = 0; i < 4; ++i)
#pragma unroll
        for (int j = 0; j < 8; ++j) acc[i][j] = 0.f;
    const float* hb = g_h + (size_t)b * ICC * HWD + s0;
    for (int kc = 0; kc < 8; ++kc) {
        for (int g = tid; g < 2048; g += 256) {
            int cl = g >> 5, kk = g & 31;
            As[kk][cl] = vmat[(c0 + cl) * ICC + kc * 32 + kk];
        }
        for (int g = tid; g < 4096; g += 256) {
            int kk = g >> 7, ss = g & 127;
            Bs[kk][ss] = hb[(size_t)(kc * 32 + kk) * HWD + ss];
        }
        __syncthreads();
#pragma unroll 8
        for (int kk = 0; kk < 32; ++kk) {
            float a0 = As[kk][ty * 4 + 0], a1 = As[kk][ty * 4 + 1];
            float a2 = As[kk][ty * 4 + 2], a3 = As[kk][ty * 4 + 3];
            float4 b0 = *(const float4*)&Bs[kk][tx * 8];
            float4 b1 = *(const float4*)&Bs[kk][tx * 8 + 4];
            float bj[8] = {b0.x, b0.y, b0.z, b0.w, b1.x, b1.y, b1.z, b1.w};
#pragma unroll
            for (int j = 0; j < 8; ++j) {
                acc[0][j] += a0 * bj[j]; acc[1][j] += a1 * bj[j];
                acc[2][j] += a2 * bj[j]; acc[3][j] += a3 * bj[j];
            }
        }
        __syncthreads();
    }
#pragma unroll
    for (int i = 0; i < 4; ++i) {
        int c = c0 + ty * 4 + i;
        float iv2 = g_inv2[c], be2 = g_beta2[c];
        size_t idx = ((size_t)b * CC + c) * HWD + s0 + tx * 8;
        float4 x0v = *(const float4*)(x + idx);
        float4 x1v = *(const float4*)(x + idx + 4);
        float4 xr0 = make_float4(x0v.x + acc[i][0], x0v.y + acc[i][1],
                                 x0v.z + acc[i][2], x0v.w + acc[i][3]);
        float4 xr1 = make_float4(x1v.x + acc[i][4], x1v.y + acc[i][5],
                                 x1v.z + acc[i][6], x1v.w + acc[i][7]);
        *(float4*)(g_xr + idx) = xr0;
        *(float4*)(g_xr + idx + 4) = xr1;
        float4 n0 = make_float4(xr0.x * iv2 + be2, xr0.y * iv2 + be2,
                                xr0.z * iv2 + be2, xr0.w * iv2 + be2);
        float4 n1 = make_float4(xr1.x * iv2 + be2, xr1.y * iv2 + be2,
                                xr1.z * iv2 + be2, xr1.w * iv2 + be2);
        *(float4*)(g_n + idx) = n0;
        *(float4*)(g_n + idx + 4) = n1;
    }
}

// ---------------- 3x3 SAME conv, f32x2 dual-rate FMA ------------------------
// Block: one image row (y) x 64 output channels for one batch image.
// 128 threads: thread = 4 oc (2 f32x2 pairs) x 8 x positions.
// MODE 0: in=g_n  -> bias + exact GELU -> g_t       (128 -> 512 ch)
// MODE 1: in=g_t  -> bias + g_xr residual -> d_out  (512 -> 128 ch)
#define CONV_CK    16
#define CONV_INROW 68
#define CONV_WROW  66
#define CONV_SMEM  ((CONV_CK * 3 * CONV_INROW + CONV_CK * 9 * CONV_WROW) * 4)

template <int MODE>
__global__ void __launch_bounds__(128) k_conv3x3(const float* __restrict__ w,
                                                 const float* __restrict__ bias,
                                                 float* __restrict__ dout) {
    constexpr int ICT = (MODE == 0) ? 128 : 512;
    const float* in = (MODE == 0) ? g_n : g_t;

    extern __shared__ float sm[];
    float* In = sm;                             // [CK][3][68], col 0 => x=-1
    float* Ws = sm + CONV_CK * 3 * CONV_INROW;  // [kk*9+tap][66] (oc along row)

    int y = blockIdx.x;
    int oc0 = blockIdx.y * 64;
    int b = blockIdx.z;
    int tid = threadIdx.x;
    int tx = tid & 7, ty = tid >> 3;
    int x0 = tx * 8;

    u64 acc01[8], acc23[8];
#pragma unroll
    for (int j = 0; j < 8; ++j) { acc01[j] = 0ULL; acc23[j] = 0ULL; }

    const float* inb = in + (size_t)b * ICT * HWD;
    const float* wb = w + (size_t)oc0 * ICT * 9;

    for (int cbase = 0; cbase < ICT; cbase += CONV_CK) {
        // stage input tile: rows y-1..y+1, x = -1..66 (zero-padded borders)
        for (int g = tid; g < CONV_CK * 3 * CONV_INROW; g += 128) {
            int kk = g / (3 * CONV_INROW);
            int rem = g - kk * (3 * CONV_INROW);
            int dy = rem / CONV_INROW;
            int col = rem - dy * CONV_INROW;
            int xx = col - 1;
            int yy = y + dy - 1;
            float val = 0.f;
            if ((unsigned)xx < 64u && (unsigned)yy < 64u)
                val = inb[(size_t)(cbase + kk) * HWD + yy * 64 + xx];
            In[(kk * 3 + dy) * CONV_INROW + col] = val;
        }
        // stage weights: [oc][(cbase+kk)*9+tap] -> smem [kk*9+tap][oc]
        for (int g = tid; g < 64 * CONV_CK * 9; g += 128) {
            int oc = g / (CONV_CK * 9);
            int rr = g - oc * (CONV_CK * 9);
            Ws[rr * CONV_WROW + oc] = wb[(size_t)oc * (ICT * 9) + cbase * 9 + rr];
        }
        __syncthreads();
#pragma unroll 2
        for (int kk = 0; kk < CONV_CK; ++kk) {
#pragma unroll
            for (int dy = 0; dy < 3; ++dy) {
                const float* ip = In + (kk * 3 + dy) * CONV_INROW + x0;
                float4 f0 = *(const float4*)ip;
                float4 f1 = *(const float4*)(ip + 4);
                float2 f2 = *(const float2*)(ip + 8);
                u64 irp[10];
                irp[0] = splat2(f0.x); irp[1] = splat2(f0.y);
                irp[2] = splat2(f0.z); irp[3] = splat2(f0.w);
                irp[4] = splat2(f1.x); irp[5] = splat2(f1.y);
                irp[6] = splat2(f1.z); irp[7] = splat2(f1.w);
                irp[8] = splat2(f2.x); irp[9] = splat2(f2.y);
#pragma unroll
                for (int dx = 0; dx < 3; ++dx) {
                    int rr = kk * 9 + dy * 3 + dx;
                    u64 w01 = *(const u64*)(Ws + rr * CONV_WROW + ty * 4);
                    u64 w23 = *(const u64*)(Ws + rr * CONV_WROW + ty * 4 + 2);
#pragma unroll
                    for (int j = 0; j < 8; ++j) {
                        fma2(acc01[j], w01, irp[j + dx]);
                        fma2(acc23[j], w23, irp[j + dx]);
                    }
                }
            }
        }
        __syncthreads();
    }

    float a[4][8];
#pragma unroll
    for (int j = 0; j < 8; ++j) {
        unpack2(acc01[j], a[0][j], a[1][j]);
        unpack2(acc23[j], a[2][j], a[3][j]);
    }

    if (MODE == 0) {
#pragma unroll
        for (int i = 0; i < 4; ++i) {
            int oc = oc0 + ty * 4 + i;
            float bb = bias[oc];
            float* op = g_t + ((size_t)b * HIDD + oc) * HWD + y * 64 + x0;
#pragma unroll
            for (int j = 0; j < 8; ++j) {
                float t = a[i][j] + bb;
                op[j] = 0.5f * t * (1.0f + erff(t * 0.70710678118654752f));
            }
        }
    } else {
#pragma unroll
        for (int i = 0; i < 4; ++i) {
            int oc = oc0 + ty * 4 + i;
            float bb = bias[oc];
            size_t idx = ((size_t)b * CC + oc) * HWD + y * 64 + x0;
            const float* xrp = g_xr + idx;
#pragma unroll
            for (int j = 0; j < 8; ++j) dout[idx + j] = a[i][j] + bb + xrp[j];
        }
    }
}

// ---------------------------------------------------------------------------
extern "C" void kernel_launch(void* const* d_in, const int* in_sizes, int n_in,
                              void* d_out, int out_size) {
    (void)in_sizes; (void)n_in; (void)out_size;
    const float* x     = (const float*)d_in[0];
    const float* bn1_g = (const float*)d_in[1];
    const float* bn1_b = (const float*)d_in[2];
    const float* bn1_m = (const float*)d_in[3];
    const float* bn1_v = (const float*)d_in[4];
    const float* kmat  = (const float*)d_in[5];
    const float* vmat  = (const float*)d_in[6];
    const float* bn2_g = (const float*)d_in[7];
    const float* bn2_b = (const float*)d_in[8];
    const float* bn2_m = (const float*)d_in[9];
    const float* bn2_v = (const float*)d_in[10];
    const float* w1    = (const float*)d_in[11];
    const float* b1    = (const float*)d_in[12];
    const float* w2    = (const float*)d_in[13];
    const float* b2    = (const float*)d_in[14];
    float* out = (float*)d_out;

    static bool attr_done = false;
    if (!attr_done) {
        cudaFuncSetAttribute(k_conv3x3<0>, cudaFuncAttributeMaxDynamicSharedMemorySize, CONV_SMEM);
        cudaFuncSetAttribute(k_conv3x3<1>, cudaFuncAttributeMaxDynamicSharedMemorySize, CONV_SMEM);
        attr_done = true;
    }

    k_fold<<<1, 256>>>(bn1_g, bn1_b, bn1_m, bn1_v, kmat,
                       bn2_g, bn2_b, bn2_m, bn2_v);

    dim3 g1(HWD / 128, ICC / 64, BB);
    k_gemm1<<<g1, 256>>>(x);

    k_rowstats<<<BB * ICC, 256>>>();

    dim3 gd(HWD / 256, 8, BB);
    k_dnorm<<<gd, 256>>>();

    dim3 g2(HWD / 128, CC / 64, BB);
    k_gemm2<<<g2, 256>>>(x, vmat);

    dim3 gc1(64, HIDD / 64, BB);
    k_conv3x3<0><<<gc1, 128, CONV_SMEM>>>(w1, b1, nullptr);

    dim3 gc2(64, CC / 64, BB);
    k_conv3x3<1><<<gc2, 128, CONV_SMEM>>>(w2, b2, out);
}